// round 17
// baseline (speedup 1.0000x reference)
#include <cuda_runtime.h>
#include <cuda_fp16.h>
#include <math.h>
#include <stdint.h>

#define N_NODES 50000
#define N_EDGES 800000
#define IN_CH   128
#define OUT_CH  64
#define BN_EPS  1e-5f

// ---------------- scratch (no allocation allowed) ----------------
__device__ float        g_h[N_NODES * OUT_CH];    // x @ W (fp32, for self-loop path)
__device__ unsigned int g_h16[N_NODES * 32];      // h as half2 pairs (scatter gather)
__device__ float        g_agg[N_NODES * OUT_CH];  // aggregated messages (edges only)
__device__ int   g_deg[N_NODES];
__device__ float g_dinv[N_NODES];
__device__ float g_sum[OUT_CH];
__device__ float g_sumsq[OUT_CH];
__device__ int   g_eidx[2 * N_EDGES];             // decoded int32 edges (src then dst)
__device__ int   g_is64;
__device__ int   g_count;                         // act_bn grid-sync counter
__device__ volatile int g_flag;                   // act_bn grid-sync flag

// ---------------- packed f32x2 FFMA ----------------
__device__ __forceinline__ void ffma2(unsigned long long& d, unsigned long long a,
                                      unsigned long long b) {
    asm("fma.rn.f32x2 %0, %1, %2, %0;" : "+l"(d) : "l"(a), "l"(b));
}
__device__ __forceinline__ unsigned long long dup2(float a) {
    unsigned long long r;
    asm("mov.b64 %0, {%1,%1};" : "=l"(r) : "f"(a));
    return r;
}
union F4U2 { float4 f; struct { unsigned long long lo, hi; } u; };
union U2F2 { unsigned long long u; struct { float lo, hi; } f; };

// ---------------- fused init + dtype sniff + sync reset ----------------
// int64 edges (values < 50000) have every odd 32-bit word zero.
__global__ void k_init_sniff(const unsigned int* __restrict__ w) {
    int i = blockIdx.x * blockDim.x + threadIdx.x;
    if (i < N_NODES) g_deg[i] = 1;                 // self loop
    if (i < OUT_CH) { g_sum[i] = 0.f; g_sumsq[i] = 0.f; }
    if (i == 0) {
        g_count = 0; g_flag = 0;
        int odd_zero = 1;
        #pragma unroll
        for (int j = 0; j < 16; j++)
            if (w[2 * j + 1] != 0u) odd_zero = 0;
        g_is64 = odd_zero;
    }
}

// ---------------- fused decode + in-degree ----------------
__global__ void k_decode_deg(const unsigned int* __restrict__ w) {
    int i = blockIdx.x * blockDim.x + threadIdx.x;
    if (i >= 2 * N_EDGES) return;
    int is64 = g_is64;
    int v = (int)(is64 ? w[2 * (size_t)i] : w[i]);
    g_eidx[i] = v;
    if (i >= N_EDGES) atomicAdd(&g_deg[v], 1);     // dst half
}

__global__ void k_dinv() {
    int i = blockIdx.x * blockDim.x + threadIdx.x;
    if (i < N_NODES) g_dinv[i] = rsqrtf((float)g_deg[i]);
}

// ================= GEMM: h[N,64] = x[N,128] @ W[128,64] =================
// Classic 8x4 micro-tile (proven R14 design). Epilogue also writes the fp16
// mirror g_h16 and zeroes g_agg rows.
#define TILE_M 128
#define SMEM_TOT ((128 * 128 + 128 * 64) * 4)     /* As 64 KB + Ws 32 KB = 96 KB */

__global__ void __launch_bounds__(256, 2) k_gemm(const float* __restrict__ x,
                                                 const float* __restrict__ W) {
    extern __shared__ float4 sm4[];
    float4* As4 = sm4;                 // [128][32] float4, swizzled
    float4* Ws4 = sm4 + 128 * 32;      // [128][16] float4 (row-major W)
    const int tid  = threadIdx.x;
    const int row0 = blockIdx.x * TILE_M;

    #pragma unroll
    for (int i = 0; i < 16; i++) {
        int idx4 = tid + i * 256;          // 4096 = 128 rows x 32 float4
        int r = idx4 >> 5, c4 = idx4 & 31;
        int gr = row0 + r;
        float4 v = make_float4(0.f, 0.f, 0.f, 0.f);
        if (gr < N_NODES) v = ((const float4*)(x + (size_t)gr * IN_CH))[c4];
        As4[r * 32 + (c4 ^ ((r >> 3) & 1))] = v;
    }
    #pragma unroll
    for (int i = 0; i < 8; i++)
        Ws4[tid + i * 256] = ((const float4*)W)[tid + i * 256];
    __syncthreads();

    const int ty = tid >> 4;           // 0..15
    const int tx = tid & 15;           // 0..15
    const int sw = ty & 1;
    unsigned long long acc[8][2] = {};
    const float4* arow = As4 + ty * 8 * 32;

    #pragma unroll 2
    for (int kg = 0; kg < 32; kg++) {  // 32 groups of 4 k
        float4 a4[8];
        #pragma unroll
        for (int i = 0; i < 8; i++)
            a4[i] = arow[i * 32 + (kg ^ sw)];
        #pragma unroll
        for (int j = 0; j < 4; j++) {
            F4U2 b; b.f = Ws4[(kg * 4 + j) * 16 + tx];
            #pragma unroll
            for (int i = 0; i < 8; i++) {
                float a = (j == 0) ? a4[i].x : (j == 1) ? a4[i].y
                         : (j == 2) ? a4[i].z : a4[i].w;
                unsigned long long aa = dup2(a);
                ffma2(acc[i][0], aa, b.u.lo);
                ffma2(acc[i][1], aa, b.u.hi);
            }
        }
    }

    const float4 z = make_float4(0.f, 0.f, 0.f, 0.f);
    #pragma unroll
    for (int i = 0; i < 8; i++) {
        int gr = row0 + ty * 8 + i;
        if (gr < N_NODES) {
            U2F2 l, h; l.u = acc[i][0]; h.u = acc[i][1];
            float4 v = make_float4(l.f.lo, l.f.hi, h.f.lo, h.f.hi);
            *(float4*)&g_h[(size_t)gr * OUT_CH + tx * 4] = v;
            *(float4*)&g_agg[(size_t)gr * OUT_CH + tx * 4] = z;
            // fp16 mirror: 2 half2 words
            unsigned int p0, p1;
            asm("cvt.rn.f16x2.f32 %0, %1, %2;" : "=r"(p0) : "f"(v.y), "f"(v.x));
            asm("cvt.rn.f16x2.f32 %0, %1, %2;" : "=r"(p1) : "f"(v.w), "f"(v.z));
            *(uint2*)&g_h16[(size_t)gr * 32 + tx * 2] = make_uint2(p0, p1);
        }
    }
}

// ------- edge scatter: 8 threads / edge, fp16 gather, fp32 v4 red -------
__global__ void __launch_bounds__(256) k_scatter() {
    long long t = (long long)blockIdx.x * blockDim.x + threadIdx.x;
    if (t >= (long long)N_EDGES * 8) return;
    int e = (int)(t >> 3), q = (int)(t & 7);
    int s = g_eidx[e];
    int d = g_eidx[N_EDGES + e];
    float norm = g_dinv[s] * g_dinv[d];
    // 8 channels = 4 half2 words = one 16B load
    uint4 hw = *(const uint4*)&g_h16[(size_t)s * 32 + q * 4];
    float2 f0 = __half22float2(*(__half2*)&hw.x);
    float2 f1 = __half22float2(*(__half2*)&hw.y);
    float2 f2 = __half22float2(*(__half2*)&hw.z);
    float2 f3 = __half22float2(*(__half2*)&hw.w);
    float* p = &g_agg[(size_t)d * OUT_CH + q * 8];
    asm volatile("red.global.add.v4.f32 [%0], {%1,%2,%3,%4};"
                 :: "l"(p), "f"(f0.x * norm), "f"(f0.y * norm),
                    "f"(f1.x * norm), "f"(f1.y * norm) : "memory");
    asm volatile("red.global.add.v4.f32 [%0], {%1,%2,%3,%4};"
                 :: "l"(p + 4), "f"(f2.x * norm), "f"(f2.y * norm),
                    "f"(f3.x * norm), "f"(f3.y * norm) : "memory");
}

// ---- fused act + batchnorm, persistent grid with counter/flag sync ----
#define AB_GRID 296
#define AB_STRIDE (AB_GRID * 256)          /* 75776, multiple of 16 */
#define AB_ITERS 11                        /* ceil(800000 / 75776) */

__global__ void __launch_bounds__(256, 2) k_act_bn(const float* __restrict__ bias,
                                                   const float* __restrict__ gamma,
                                                   const float* __restrict__ beta,
                                                   float* __restrict__ out) {
    const int tid = threadIdx.x;
    const int cg = tid & 15;
    const float4 b4 = ((const float4*)bias)[cg];
    const int total4 = N_NODES * 16;
    const int base = blockIdx.x * 256 + tid;

    float4 vals[AB_ITERS];
    float4 s  = make_float4(0.f, 0.f, 0.f, 0.f);
    float4 s2 = make_float4(0.f, 0.f, 0.f, 0.f);

    {
        int i = base;
        #pragma unroll
        for (int j = 0; j < AB_ITERS; j++, i += AB_STRIDE) {
            if (i < total4) {
                int n = i >> 4;
                float di = g_dinv[n];
                float sl = di * di;
                float4 a = ((const float4*)g_agg)[i];
                float4 h = ((const float4*)g_h)[i];
                float4 v;
                v.x = tanhf(a.x + sl * h.x + b4.x);
                v.y = tanhf(a.y + sl * h.y + b4.y);
                v.z = tanhf(a.z + sl * h.z + b4.z);
                v.w = tanhf(a.w + sl * h.w + b4.w);
                vals[j] = v;
                s.x += v.x; s.y += v.y; s.z += v.z; s.w += v.w;
                s2.x += v.x * v.x; s2.y += v.y * v.y; s2.z += v.z * v.z; s2.w += v.w * v.w;
            }
        }
    }

    __shared__ float4 sh[256];
    sh[tid] = s; __syncthreads();
    if (tid < 16) {
        float4 acc = sh[tid];
        #pragma unroll
        for (int j = 1; j < 16; j++) {
            float4 o = sh[tid + 16 * j];
            acc.x += o.x; acc.y += o.y; acc.z += o.z; acc.w += o.w;
        }
        atomicAdd(&g_sum[cg * 4 + 0], acc.x);
        atomicAdd(&g_sum[cg * 4 + 1], acc.y);
        atomicAdd(&g_sum[cg * 4 + 2], acc.z);
        atomicAdd(&g_sum[cg * 4 + 3], acc.w);
    }
    __syncthreads();
    sh[tid] = s2; __syncthreads();
    if (tid < 16) {
        float4 acc = sh[tid];
        #pragma unroll
        for (int j = 1; j < 16; j++) {
            float4 o = sh[tid + 16 * j];
            acc.x += o.x; acc.y += o.y; acc.z += o.z; acc.w += o.w;
        }
        atomicAdd(&g_sumsq[cg * 4 + 0], acc.x);
        atomicAdd(&g_sumsq[cg * 4 + 1], acc.y);
        atomicAdd(&g_sumsq[cg * 4 + 2], acc.z);
        atomicAdd(&g_sumsq[cg * 4 + 3], acc.w);
    }
    __syncthreads();

    if (tid == 0) {
        __threadfence();
        int o = atomicAdd(&g_count, 1);
        if (o == AB_GRID - 1) atomicExch((int*)&g_flag, 1);
        while (g_flag == 0) __nanosleep(64);
    }
    __syncthreads();
    __threadfence();

    float4 sc, sf;
    {
        const float invN = 1.0f / (float)N_NODES;
        float4 su = __ldcg(&((const float4*)g_sum)[cg]);
        float4 sq = __ldcg(&((const float4*)g_sumsq)[cg]);
        float4 g4 = ((const float4*)gamma)[cg];
        float4 be4 = ((const float4*)beta)[cg];
        float mx = su.x * invN, my = su.y * invN, mz = su.z * invN, mw = su.w * invN;
        sc.x = g4.x * rsqrtf(sq.x * invN - mx * mx + BN_EPS);
        sc.y = g4.y * rsqrtf(sq.y * invN - my * my + BN_EPS);
        sc.z = g4.z * rsqrtf(sq.z * invN - mz * mz + BN_EPS);
        sc.w = g4.w * rsqrtf(sq.w * invN - mw * mw + BN_EPS);
        sf.x = be4.x - mx * sc.x;
        sf.y = be4.y - my * sc.y;
        sf.z = be4.z - mz * sc.z;
        sf.w = be4.w - mw * sc.w;
    }
    {
        int i = base;
        #pragma unroll
        for (int j = 0; j < AB_ITERS; j++, i += AB_STRIDE) {
            if (i < total4) {
                float4 v = vals[j];
                v.x = v.x * sc.x + sf.x;
                v.y = v.y * sc.y + sf.y;
                v.z = v.z * sc.z + sf.z;
                v.w = v.w * sc.w + sf.w;
                ((float4*)out)[i] = v;
            }
        }
    }
}

// ---------------- streams/events (created once; no device memory) ----------------
static struct SideStream {
    cudaStream_t s;
    cudaEvent_t fork_ev, join_ev;
    SideStream() {
        cudaStreamCreateWithFlags(&s, cudaStreamNonBlocking);
        cudaEventCreateWithFlags(&fork_ev, cudaEventDisableTiming);
        cudaEventCreateWithFlags(&join_ev, cudaEventDisableTiming);
        cudaFuncSetAttribute(k_gemm, cudaFuncAttributeMaxDynamicSharedMemorySize, SMEM_TOT);
    }
} g_ss;

// ---------------- launch ----------------
extern "C" void kernel_launch(void* const* d_in, const int* in_sizes, int n_in,
                              void* d_out, int out_size) {
    const float*        x     = (const float*)d_in[0];
    const unsigned int* ei    = (const unsigned int*)d_in[1];  // int32 or int64, sniffed
    const float*        W     = (const float*)d_in[2];
    const float*        bias  = (const float*)d_in[3];
    const float*        gamma = (const float*)d_in[4];
    const float*        beta  = (const float*)d_in[5];
    float*              out   = (float*)d_out;

    static bool attr_done = false;
    if (!attr_done) {   // first call is outside graph capture
        cudaFuncSetAttribute(k_gemm, cudaFuncAttributeMaxDynamicSharedMemorySize, SMEM_TOT);
        attr_done = true;
    }

    // fork: edge chain on side stream, overlapped with GEMM on main stream
    cudaEventRecord(g_ss.fork_ev, 0);
    cudaStreamWaitEvent(g_ss.s, g_ss.fork_ev, 0);

    k_init_sniff<<<(N_NODES + 255) / 256, 256, 0, g_ss.s>>>(ei);
    k_decode_deg<<<(2 * N_EDGES + 255) / 256, 256, 0, g_ss.s>>>(ei);
    k_dinv<<<(N_NODES + 255) / 256, 256, 0, g_ss.s>>>();
    cudaEventRecord(g_ss.join_ev, g_ss.s);

    k_gemm<<<(N_NODES + TILE_M - 1) / TILE_M, 256, SMEM_TOT>>>(x, W);

    // join, then scatter + fused act/bn on main stream
    cudaStreamWaitEvent(0, g_ss.join_ev, 0);
    k_scatter<<<(int)(((long long)N_EDGES * 8 + 255) / 256), 256>>>();
    k_act_bn<<<AB_GRID, 256>>>(bias, gamma, beta, out);
}